// round 1
// baseline (speedup 1.0000x reference)
#include <cuda_runtime.h>
#include <cstdint>

#define HID   32
#define NCOL  224      // 7*HID gate columns
#define TPB   224      // one thread per column; warp w == gate w
#define NSTEP 2047     // S-1
#define NB    512
#define SEQ   2048
#define NTY   20
#define BETA  0.1f

typedef unsigned long long ull;

__device__ __forceinline__ unsigned su32(const void* p) {
    return (unsigned)__cvta_generic_to_shared(p);
}
// packed fp32x2 FMA (sm_100+): 2 full-precision fp32 MACs per instruction
__device__ __forceinline__ void ffma2(ull& d, ull a, ull b) {
    asm("fma.rn.f32x2 %0, %1, %2, %0;" : "+l"(d) : "l"(a), "l"(b));
}
__device__ __forceinline__ ull fadd2(ull a, ull b) {
    ull d; asm("add.rn.f32x2 %0, %1, %2;" : "=l"(d) : "l"(a), "l"(b)); return d;
}
__device__ __forceinline__ ull pack2(float a, float b) {
    ull d; asm("mov.b64 %0, {%1, %2};" : "=l"(d) : "f"(a), "f"(b)); return d;
}
__device__ __forceinline__ void unpack2(ull v, float& a, float& b) {
    asm("mov.b64 {%0, %1}, %2;" : "=f"(a), "=f"(b) : "l"(v));
}
// 128-bit shared load straight into two aligned 64-bit regs (feeds ffma2 directly)
__device__ __forceinline__ void lds128(ull& a, ull& b, unsigned addr) {
    asm volatile("ld.shared.v2.u64 {%0, %1}, [%2];" : "=l"(a), "=l"(b) : "r"(addr));
}

__device__ __forceinline__ float tanh_fast(float x) {
    // overflow-safe: e in (0,1]
    float e = __expf(-2.f * fabsf(x));
    float t = __fdividef(1.f - e, 1.f + e);
    return copysignf(t, x);
}
__device__ __forceinline__ float sigmoid_fast(float x) {
    return __fdividef(1.f, 1.f + __expf(-x));
}

__global__ __launch_bounds__(TPB, 4)
void hawkes_kernel(const int* __restrict__ types,
                   const float* __restrict__ dtime,
                   const float* __restrict__ emb,
                   const float* __restrict__ W,
                   const float* __restrict__ bvec,
                   float* __restrict__ out)
{
    __shared__ float s_gx[NTY * NCOL];          // per-type x-side gate pre-activation (incl. bias)
    __shared__ __align__(16) float s_h[HID];    // current hidden state
    __shared__ float s_act[NCOL];               // per-column activations
    __shared__ int   s_ty[NSTEP];               // this sample's event types
    __shared__ float s_dt[NSTEP];               // this sample's dtimes (shifted by 1)
    __shared__ float s_emb[NTY * HID];

    const int tid = threadIdx.x;
    const int bs  = blockIdx.x;

    // ---- prologue: stage per-sample streams + embedding table ----
    for (int i = tid; i < NTY * HID; i += TPB) s_emb[i] = emb[i];
    for (int t = tid; t < NSTEP; t += TPB) {
        s_ty[t] = types[bs * SEQ + t];
        s_dt[t] = dtime[bs * SEQ + t + 1];
    }
    if (tid < HID) s_h[tid] = 0.f;
    __syncthreads();

    // ---- per-column weights: build gx lookup table, pack Wh into registers ----
    {
        float bcol = bvec[tid];
        float wx[HID];
        #pragma unroll
        for (int k = 0; k < HID; k++) wx[k] = W[k * NCOL + tid];
        for (int ty = 0; ty < NTY; ty++) {
            float acc = bcol;
            #pragma unroll
            for (int k = 0; k < HID; k++) acc += s_emb[ty * HID + k] * wx[k];
            s_gx[ty * NCOL + tid] = acc;
        }
    }
    ull whp[HID / 2];   // whp[k] = { W_h[2k][col], W_h[2k+1][col] }
    #pragma unroll
    for (int k = 0; k < HID / 2; k++)
        whp[k] = pack2(W[(HID + 2 * k) * NCOL + tid],
                       W[(HID + 2 * k + 1) * NCOL + tid]);
    __syncthreads();

    const unsigned hb = su32(s_h);
    const int gate = tid >> 5;     // warp-uniform
    const int lane = tid & 31;
    float c = 0.f, cbar = 0.f;     // recurrent cell state (warp 0 lanes only use these)

    const size_t O1 = (size_t)NSTEP * NB * HID;
    size_t obase = (size_t)bs * HID + lane;

    for (int t = 0; t < NSTEP; t++) {
        const int ty = s_ty[t];

        // g_col = gx_table[ty][col] + h . W_h[:,col]   (packed fp32x2, full precision)
        ull a0 = 0, a1 = 0;
        #pragma unroll
        for (int q = 0; q < 8; q++) {
            ull hA, hB;
            lds128(hA, hB, hb + q * 16);       // broadcast, conflict-free
            ffma2(a0, hA, whp[2 * q]);
            ffma2(a1, hB, whp[2 * q + 1]);
        }
        float glo, ghi;
        unpack2(fadd2(a0, a1), glo, ghi);
        const float g = s_gx[ty * NCOL + tid] + glo + ghi;

        // activation — warp-uniform branch (warp == gate)
        float a;
        if (gate == 2) {                         // z = tanh
            a = tanh_fast(g);
        } else if (gate == 6) {                  // delta = softplus(beta*g)/beta
            float y = BETA * g;
            a = (fmaxf(y, 0.f) + log1pf(__expf(-fabsf(y)))) * (1.f / BETA);
            out[3 * O1 + obase] = a;             // decay_out written by owning warp
        } else {                                 // i, f, o, ib, fb = sigmoid
            a = sigmoid_fast(g);
            if (gate == 3) out[4 * O1 + obase] = a;   // gate_out (o_g)
        }
        s_act[tid] = a;
        __syncthreads();

        // combine + state update: warp 0 (one lane per hidden unit)
        if (tid < HID) {
            const float ig  = s_act[tid];
            const float fg  = s_act[HID + tid];
            const float zg  = s_act[2 * HID + tid];
            const float og  = s_act[3 * HID + tid];
            const float ibg = s_act[4 * HID + tid];
            const float fbg = s_act[5 * HID + tid];
            const float del = s_act[6 * HID + tid];
            const float dt  = s_dt[t];

            const float cn  = fg * c + ig * zg;
            const float cbn = fbg * cbar + ibg * zg;
            const float ct  = cbn + (cn - cbn) * __expf(-del * dt);
            const float hn  = og * tanh_fast(ct);

            c = ct; cbar = cbn;
            s_h[tid] = hn;

            out[obase]          = hn;    // h_out
            out[O1 + obase]     = cn;    // c_out
            out[2 * O1 + obase] = cbn;   // c_bar_out
        }
        obase += (size_t)NB * HID;
        __syncthreads();                 // h_new visible to all gate warps
    }
}

extern "C" void kernel_launch(void* const* d_in, const int* in_sizes, int n_in,
                              void* d_out, int out_size)
{
    const int*   types = (const int*)d_in[0];
    const float* dtime = (const float*)d_in[1];
    const float* emb   = (const float*)d_in[2];
    const float* W     = (const float*)d_in[3];
    const float* bvec  = (const float*)d_in[4];
    hawkes_kernel<<<NB, TPB>>>(types, dtime, emb, W, bvec, (float*)d_out);
}